// round 9
// baseline (speedup 1.0000x reference)
#include <cuda_runtime.h>
#include <cuda_bf16.h>
#include <cstdint>

#define DIN   128
#define DOUT  128
#define MAXN  100000
#define BN_EPS 1e-5f

// Scratch (allocation-free rule: __device__ globals)
__device__ float g_y1[(size_t)MAXN * DIN];     // Y1 = feat @ W1  [N,128]
__device__ int   g_rowptr[MAXN + 1];
// [0..255]=colsum, [256..511]=colsumsq, [512..767]=scale, [768..1023]=shift
__device__ float g_stats[1024];

// ---------------------------------------------------------------------------
__device__ __forceinline__ void ffma2(unsigned long long& d,
                                      unsigned long long a,
                                      unsigned long long b) {
    asm("fma.rn.f32x2 %0, %1, %2, %3;" : "=l"(d) : "l"(a), "l"(b), "l"(d));
}
__device__ __forceinline__ unsigned long long pack2(float x) {
    unsigned long long r;
    unsigned int u = __float_as_uint(x);
    asm("mov.b64 %0, {%1, %1};" : "=l"(r) : "r"(u));
    return r;
}
__device__ __forceinline__ float f2lo(unsigned long long x) {
    return __uint_as_float((unsigned int)(x & 0xFFFFFFFFull));
}
__device__ __forceinline__ float f2hi(unsigned long long x) {
    return __uint_as_float((unsigned int)(x >> 32));
}

// ---------------------------------------------------------------------------
__global__ void zero_stats_kernel() {
    g_stats[threadIdx.x] = 0.0f;          // 512 threads
}

// adj_rows is sorted; scatter row boundaries into CSR row_ptr.
__global__ void build_rowptr_kernel(const int* __restrict__ rows, int E, int N) {
    int e = blockIdx.x * blockDim.x + threadIdx.x;
    if (e >= E) return;
    int r = rows[e];
    int prev = (e == 0) ? -1 : rows[e - 1];
    for (int rr = prev + 1; rr <= r; rr++) g_rowptr[rr] = e;
    if (e == E - 1) {
        for (int rr = r + 1; rr <= N; rr++) g_rowptr[rr] = E;
    }
}

// ---------------------------------------------------------------------------
// Double-GEMM: one pass over feat computes
//   p0 = relu(feat@W0)+b0  -> out[:,0:128]  (+ BN column stats)
//   Y1 = feat@W1           -> g_y1          (raw; SpMM consumes it)
// Tile M=128, N=256 (128 per W), 512 threads, 8x8 micro-tile per thread.
// FFMA2 accumulators paired along COLUMNS: b-pairs free from Bs float4 LDS;
// a duplicated once into SMEM as u64 {a,a} (warp-broadcast reads).
// SMEM layout (aliased views of one 33KB block; tiles dead before sred use):
//   [0 .. 16640)        As2: u64[16][130]
//   [16640 .. 33024)    Bs:  float[16][256]
//   [0 .. 8192)         sred_s: float[16][128]   (epilogue only)
//   [8192 .. 16384)     sred_q: float[16][128]   (epilogue only)
#define AS2_WORDS (16 * 130)
__global__ __launch_bounds__(512, 1)
void dgemm_kernel(const float* __restrict__ X,
                  const float* __restrict__ W0,
                  const float* __restrict__ W1,
                  const float* __restrict__ b0,
                  float* __restrict__ out,
                  int N) {
    __shared__ __align__(16) char smem_raw[AS2_WORDS * 8 + 16 * 256 * 4];
    unsigned long long (*As2)[130] = (unsigned long long (*)[130])smem_raw;
    float (*Bs)[256] = (float (*)[256])(smem_raw + AS2_WORDS * 8);
    float (*sred_s)[128] = (float (*)[128])smem_raw;
    float (*sred_q)[128] = (float (*)[128])(smem_raw + 8192);

    int tid = threadIdx.x;
    int tx = tid & 31;                  // 32 col groups of 4+4
    int ty = tid >> 5;                  // 16 row groups of 8
    int m0 = blockIdx.x * 128;

    // acc2[i][p]: row i (0..7), p: 0,1 = W0 col-pairs {tx*4,+1},{+2,+3};
    //                            2,3 = W1 col-pairs (same cols in Y1)
    unsigned long long acc2[8][4];
#pragma unroll
    for (int i = 0; i < 8; i++)
#pragma unroll
        for (int p = 0; p < 4; p++) acc2[i][p] = 0ull;

    for (int k0 = 0; k0 < DIN; k0 += 16) {
        // A tile: 128 rows x 16 k, duplicated-transposed into As2[k][m]
        {
            int row = tid >> 2;              // 0..127
            int kq  = (tid & 3) * 4;         // 0,4,8,12
            int gr  = m0 + row;
            float4 v = make_float4(0.f, 0.f, 0.f, 0.f);
            if (gr < N)
                v = *(const float4*)&X[(size_t)gr * DIN + k0 + kq];
            As2[kq + 0][row] = pack2(v.x);
            As2[kq + 1][row] = pack2(v.y);
            As2[kq + 2][row] = pack2(v.z);
            As2[kq + 3][row] = pack2(v.w);
        }
        // B tile: 16 k x 256 n  (n<128 from W0, else W1)
        {
            int q  = tid & 63;               // quad index 0..63
            int kr = tid >> 6;               // 0..7
            int c4 = q * 4;
#pragma unroll
            for (int h = 0; h < 2; h++) {
                int k = kr + h * 8;
                const float* src = (c4 < 128)
                    ? &W0[(size_t)(k0 + k) * DOUT + c4]
                    : &W1[(size_t)(k0 + k) * DOUT + (c4 - 128)];
                *(float4*)&Bs[k][c4] = *(const float4*)src;
            }
        }
        __syncthreads();

#pragma unroll
        for (int kk = 0; kk < 16; kk++) {
            // a: 8 duplicated row values, warp-broadcast (ty uniform in warp)
            unsigned long long aa[8];
            ulonglong2 t0 = *(const ulonglong2*)&As2[kk][ty * 8 + 0];
            ulonglong2 t1 = *(const ulonglong2*)&As2[kk][ty * 8 + 2];
            ulonglong2 t2 = *(const ulonglong2*)&As2[kk][ty * 8 + 4];
            ulonglong2 t3 = *(const ulonglong2*)&As2[kk][ty * 8 + 6];
            aa[0] = t0.x; aa[1] = t0.y; aa[2] = t1.x; aa[3] = t1.y;
            aa[4] = t2.x; aa[5] = t2.y; aa[6] = t3.x; aa[7] = t3.y;
            // b: col-pairs straight from float4 SMEM (no packing)
            ulonglong2 bA = *(const ulonglong2*)&Bs[kk][tx * 4];
            ulonglong2 bB = *(const ulonglong2*)&Bs[kk][128 + tx * 4];
            unsigned long long bp[4] = { bA.x, bA.y, bB.x, bB.y };
#pragma unroll
            for (int i = 0; i < 8; i++)
#pragma unroll
                for (int p = 0; p < 4; p++)
                    ffma2(acc2[i][p], aa[i], bp[p]);
        }
        __syncthreads();
    }

    // Epilogue (tiles now dead; sred aliases them)
    float4 b0v = *(const float4*)&b0[tx * 4];
    float psum[4] = {0.f, 0.f, 0.f, 0.f};
    float psq[4]  = {0.f, 0.f, 0.f, 0.f};

#pragma unroll
    for (int i = 0; i < 8; i++) {
        int m = m0 + ty * 8 + i;
        if (m >= N) continue;
        // p0 half: relu + bias + stats
        float r0 = fmaxf(f2lo(acc2[i][0]), 0.f) + b0v.x;
        float r1 = fmaxf(f2hi(acc2[i][0]), 0.f) + b0v.y;
        float r2 = fmaxf(f2lo(acc2[i][1]), 0.f) + b0v.z;
        float r3 = fmaxf(f2hi(acc2[i][1]), 0.f) + b0v.w;
        *(float4*)&out[(size_t)m * (2 * DOUT) + tx * 4] =
            make_float4(r0, r1, r2, r3);
        psum[0] += r0; psq[0] = fmaf(r0, r0, psq[0]);
        psum[1] += r1; psq[1] = fmaf(r1, r1, psq[1]);
        psum[2] += r2; psq[2] = fmaf(r2, r2, psq[2]);
        psum[3] += r3; psq[3] = fmaf(r3, r3, psq[3]);
        // Y1 half: raw
        *(float4*)&g_y1[(size_t)m * DIN + tx * 4] =
            make_float4(f2lo(acc2[i][2]), f2hi(acc2[i][2]),
                        f2lo(acc2[i][3]), f2hi(acc2[i][3]));
    }

    // Stats: conflict-free shared staging (thread slot unique), then 1 pass
    *(float4*)&sred_s[ty][tx * 4] = make_float4(psum[0], psum[1], psum[2], psum[3]);
    *(float4*)&sred_q[ty][tx * 4] = make_float4(psq[0], psq[1], psq[2], psq[3]);
    __syncthreads();
    if (tid < 128) {
        float s = 0.f, q = 0.f;
#pragma unroll
        for (int w = 0; w < 16; w++) { s += sred_s[w][tid]; q += sred_q[w][tid]; }
        atomicAdd(&g_stats[tid], s);
        atomicAdd(&g_stats[256 + tid], q);
    }
}

// ---------------------------------------------------------------------------
// Fused SpMM: p1[n] = relu(sum_e val*Y1[col]) + b1 -> out[:,128:256].
// One warp per node, lane owns a float4. 4-edge unroll.
__global__ __launch_bounds__(256)
void spmm_fused_kernel(const float* __restrict__ vals,
                       const int*   __restrict__ cols,
                       const float* __restrict__ b1,
                       float* __restrict__ out,
                       int N) {
    int warp = (blockIdx.x * blockDim.x + threadIdx.x) >> 5;
    int lane = threadIdx.x & 31;
    if (warp >= N) return;
    int s = g_rowptr[warp];
    int e = g_rowptr[warp + 1];
    float4 acc0 = make_float4(0.f, 0.f, 0.f, 0.f);
    float4 acc1 = make_float4(0.f, 0.f, 0.f, 0.f);
    int t = s;
    for (; t + 3 < e; t += 4) {
        float v0 = __ldg(&vals[t]),     v1 = __ldg(&vals[t + 1]);
        float v2 = __ldg(&vals[t + 2]), v3 = __ldg(&vals[t + 3]);
        int c0 = __ldg(&cols[t]),     c1 = __ldg(&cols[t + 1]);
        int c2 = __ldg(&cols[t + 2]), c3 = __ldg(&cols[t + 3]);
        float4 x0 = __ldg(&((const float4*)&g_y1[(size_t)c0 * DIN])[lane]);
        float4 x1 = __ldg(&((const float4*)&g_y1[(size_t)c1 * DIN])[lane]);
        float4 x2 = __ldg(&((const float4*)&g_y1[(size_t)c2 * DIN])[lane]);
        float4 x3 = __ldg(&((const float4*)&g_y1[(size_t)c3 * DIN])[lane]);
        acc0.x = fmaf(v0, x0.x, acc0.x); acc0.y = fmaf(v0, x0.y, acc0.y);
        acc0.z = fmaf(v0, x0.z, acc0.z); acc0.w = fmaf(v0, x0.w, acc0.w);
        acc1.x = fmaf(v1, x1.x, acc1.x); acc1.y = fmaf(v1, x1.y, acc1.y);
        acc1.z = fmaf(v1, x1.z, acc1.z); acc1.w = fmaf(v1, x1.w, acc1.w);
        acc0.x = fmaf(v2, x2.x, acc0.x); acc0.y = fmaf(v2, x2.y, acc0.y);
        acc0.z = fmaf(v2, x2.z, acc0.z); acc0.w = fmaf(v2, x2.w, acc0.w);
        acc1.x = fmaf(v3, x3.x, acc1.x); acc1.y = fmaf(v3, x3.y, acc1.y);
        acc1.z = fmaf(v3, x3.z, acc1.z); acc1.w = fmaf(v3, x3.w, acc1.w);
    }
    for (; t < e; t++) {
        float v0 = __ldg(&vals[t]);
        int   c0 = __ldg(&cols[t]);
        float4 x0 = __ldg(&((const float4*)&g_y1[(size_t)c0 * DIN])[lane]);
        acc0.x = fmaf(v0, x0.x, acc0.x); acc0.y = fmaf(v0, x0.y, acc0.y);
        acc0.z = fmaf(v0, x0.z, acc0.z); acc0.w = fmaf(v0, x0.w, acc0.w);
    }
    float4 bb = __ldg(&((const float4*)b1)[lane]);
    float4 r;
    r.x = fmaxf(acc0.x + acc1.x, 0.f) + bb.x;
    r.y = fmaxf(acc0.y + acc1.y, 0.f) + bb.y;
    r.z = fmaxf(acc0.z + acc1.z, 0.f) + bb.z;
    r.w = fmaxf(acc0.w + acc1.w, 0.f) + bb.w;
    *(float4*)&out[(size_t)warp * (2 * DOUT) + DOUT + lane * 4] = r;
}

// ---------------------------------------------------------------------------
// Column sum/sumsq over out[:,128:256] (L2-resident, just written by spmm).
__global__ void p1_stats_kernel(const float* __restrict__ out, int N) {
    __shared__ float ss[256], sq[256];
    int tid = threadIdx.x;
    int c   = tid & 127;
    int rh  = tid >> 7;
    int chunk = (N + gridDim.x - 1) / gridDim.x;
    int r0 = blockIdx.x * chunk;
    int r1 = r0 + chunk; if (r1 > N) r1 = N;
    float s = 0.f, q = 0.f;
    for (int r = r0 + rh; r < r1; r += 2) {
        float v = __ldg(&out[(size_t)r * (2 * DOUT) + DOUT + c]);
        s += v;
        q = fmaf(v, v, q);
    }
    ss[tid] = s; sq[tid] = q;
    __syncthreads();
    if (tid < 128) {
        s = ss[tid] + ss[tid + 128];
        q = sq[tid] + sq[tid + 128];
        atomicAdd(&g_stats[128 + tid], s);
        atomicAdd(&g_stats[384 + tid], q);
    }
}

// ---------------------------------------------------------------------------
__global__ void bn_finalize_half_kernel(const float* __restrict__ gamma,
                                        const float* __restrict__ beta,
                                        int N, int base) {
    int c = base + threadIdx.x;             // 128 threads
    float inv_n = 1.0f / (float)N;
    float mean = g_stats[c] * inv_n;
    float var  = g_stats[256 + c] * inv_n - mean * mean;
    float s = gamma[c] * rsqrtf(var + BN_EPS);
    g_stats[512 + c] = s;
    g_stats[768 + c] = beta[c] - mean * s;
}

// Normalize one 128-col half of out. half=0 -> cols 0..127, half=1 -> 128..255.
__global__ void bn_apply_half_kernel(float* __restrict__ out, int N, int half) {
    size_t total = (size_t)N * 32;          // float4s in this half
    size_t i = (size_t)blockIdx.x * blockDim.x + threadIdx.x;
    size_t stride = (size_t)gridDim.x * blockDim.x;
    const float4* scale4 = (const float4*)&g_stats[512];
    const float4* shift4 = (const float4*)&g_stats[768];
    for (; i < total; i += stride) {
        size_t row = i >> 5;
        int    q   = (int)(i & 31);
        int    c4  = half * 32 + q;
        float4 s  = scale4[c4];
        float4 sh = shift4[c4];
        size_t idx = row * 64 + c4;
        float4 v = ((float4*)out)[idx];
        v.x = fmaf(v.x, s.x, sh.x);
        v.y = fmaf(v.y, s.y, sh.y);
        v.z = fmaf(v.z, s.z, sh.z);
        v.w = fmaf(v.w, s.w, sh.w);
        ((float4*)out)[idx] = v;
    }
}

// ---------------------------------------------------------------------------
extern "C" void kernel_launch(void* const* d_in, const int* in_sizes, int n_in,
                              void* d_out, int out_size) {
    const float* feat     = (const float*)d_in[0];
    const float* adj_vals = (const float*)d_in[1];
    const float* W0       = (const float*)d_in[2];
    const float* W1       = (const float*)d_in[3];
    const float* b0       = (const float*)d_in[4];
    const float* b1       = (const float*)d_in[5];
    const float* gamma    = (const float*)d_in[6];
    const float* beta     = (const float*)d_in[7];
    const int*   adj_rows = (const int*)d_in[8];
    const int*   adj_cols = (const int*)d_in[9];
    float* out = (float*)d_out;

    int N = in_sizes[0] / DIN;
    int E = in_sizes[1];

    // Side stream + events, created once on the eager correctness call
    // (before graph capture), reused inside capture via event fork/join.
    // IMPORTANT capture rule: s1 may only receive work AFTER waiting on an
    // event recorded in the capture-origin stream (fork), and must be joined
    // back via an event the origin stream waits on.
    static cudaStream_t s1 = nullptr;
    static cudaEvent_t  eZ = nullptr, eR = nullptr, eD = nullptr, eA0 = nullptr;
    if (s1 == nullptr) {
        cudaStreamCreateWithFlags(&s1, cudaStreamNonBlocking);
        cudaEventCreateWithFlags(&eZ,  cudaEventDisableTiming);
        cudaEventCreateWithFlags(&eR,  cudaEventDisableTiming);
        cudaEventCreateWithFlags(&eD,  cudaEventDisableTiming);
        cudaEventCreateWithFlags(&eA0, cudaEventDisableTiming);
    }

    int gblocks = (N + 127) / 128;
    int sblocks = (N * 32 + 255) / 256;
    int ablocks = (N * 32 + 255) / 256;
    if (ablocks > 8192) ablocks = 8192;

    // main: zero stats, then FORK
    zero_stats_kernel<<<1, 512>>>();
    cudaEventRecord(eZ, 0);

    // side (forked): rowptr overlaps dgemm
    cudaStreamWaitEvent(s1, eZ, 0);
    build_rowptr_kernel<<<(E + 255) / 256, 256, 0, s1>>>(adj_rows, E, N);
    cudaEventRecord(eR, s1);

    // main: dgemm
    dgemm_kernel<<<gblocks, 512>>>(feat, W0, W1, b0, out, N);
    cudaEventRecord(eD, 0);

    // side: p0's BN half runs during spmm (tiny kernels, can co-reside)
    cudaStreamWaitEvent(s1, eD, 0);
    bn_finalize_half_kernel<<<1, 128, 0, s1>>>(gamma, beta, N, 0);
    bn_apply_half_kernel<<<ablocks, 256, 0, s1>>>(out, N, 0);
    cudaEventRecord(eA0, s1);

    // main: spmm (needs rowptr + Y1) -> p1 stats -> p1 BN half
    cudaStreamWaitEvent(0, eR, 0);
    spmm_fused_kernel<<<sblocks, 256>>>(adj_vals, adj_cols, b1, out, N);
    p1_stats_kernel<<<256, 256>>>(out, N);
    bn_finalize_half_kernel<<<1, 128>>>(gamma, beta, N, 128);
    bn_apply_half_kernel<<<ablocks, 256>>>(out, N, 1);

    // join side branch before capture ends
    cudaStreamWaitEvent(0, eA0, 0);
}

// round 10
// speedup vs baseline: 1.1374x; 1.1374x over previous
#include <cuda_runtime.h>
#include <cuda_bf16.h>
#include <cstdint>

#define DIN   128
#define DOUT  128
#define MAXN  100000
#define BN_EPS 1e-5f

// Scratch (allocation-free rule: __device__ globals)
__device__ float g_y1[(size_t)MAXN * DIN];     // Y1 = feat @ W1  [N,128]
__device__ int   g_rowptr[MAXN + 1];
// [0..255]=colsum, [256..511]=colsumsq, [512..767]=scale, [768..1023]=shift
__device__ float g_stats[1024];

// ---------------------------------------------------------------------------
__device__ __forceinline__ void ffma2(unsigned long long& d,
                                      unsigned long long a,
                                      unsigned long long b) {
    asm("fma.rn.f32x2 %0, %1, %2, %3;" : "=l"(d) : "l"(a), "l"(b), "l"(d));
}
__device__ __forceinline__ unsigned long long pack2(float x) {
    unsigned long long r;
    unsigned int u = __float_as_uint(x);
    asm("mov.b64 %0, {%1, %1};" : "=l"(r) : "r"(u));
    return r;
}
__device__ __forceinline__ float f2lo(unsigned long long x) {
    return __uint_as_float((unsigned int)(x & 0xFFFFFFFFull));
}
__device__ __forceinline__ float f2hi(unsigned long long x) {
    return __uint_as_float((unsigned int)(x >> 32));
}

// ---------------------------------------------------------------------------
__global__ void zero_stats_kernel() {
    g_stats[threadIdx.x] = 0.0f;          // 512 threads
}

// adj_rows is sorted; scatter row boundaries into CSR row_ptr.
__global__ void build_rowptr_kernel(const int* __restrict__ rows, int E, int N) {
    int e = blockIdx.x * blockDim.x + threadIdx.x;
    if (e >= E) return;
    int r = rows[e];
    int prev = (e == 0) ? -1 : rows[e - 1];
    for (int rr = prev + 1; rr <= r; rr++) g_rowptr[rr] = e;
    if (e == E - 1) {
        for (int rr = r + 1; rr <= N; rr++) g_rowptr[rr] = E;
    }
}

// ---------------------------------------------------------------------------
// Double-GEMM, M=64 x N=256 tile, 256 threads, 2 CTAs/SM (barrier drains of
// one CTA hidden by the other; this was the R9 regression).
//   p0 = relu(feat@W0)+b0  -> out[:,0:128]  (+ BN column stats)
//   Y1 = feat@W1           -> g_y1          (raw; SpMM consumes it)
// FFMA2 accumulators paired along COLUMNS: b-pairs free from Bs float4 LDS;
// a duplicated once into SMEM as u64 {a,a} (warp-broadcast reads).
// SMEM (24.8KB/CTA, aliased views; tiles dead before sred use):
//   [0 .. 8448)        As2: u64[16][66]
//   [8448 .. 24832)    Bs:  float[16][256]
//   [0 .. 4096)        sred_s: float[8][128]    (epilogue only)
//   [4096 .. 8192)     sred_q: float[8][128]    (epilogue only)
#define AS2_WORDS (16 * 66)
__global__ __launch_bounds__(256, 2)
void dgemm_kernel(const float* __restrict__ X,
                  const float* __restrict__ W0,
                  const float* __restrict__ W1,
                  const float* __restrict__ b0,
                  float* __restrict__ out,
                  int N) {
    __shared__ __align__(16) char smem_raw[AS2_WORDS * 8 + 16 * 256 * 4];
    unsigned long long (*As2)[66] = (unsigned long long (*)[66])smem_raw;
    float (*Bs)[256] = (float (*)[256])(smem_raw + AS2_WORDS * 8);
    float (*sred_s)[128] = (float (*)[128])smem_raw;
    float (*sred_q)[128] = (float (*)[128])(smem_raw + 4096);

    int tid = threadIdx.x;
    int tx = tid & 31;                  // 32 col groups (8 cols each)
    int ty = tid >> 5;                  // 8 row groups (8 rows each)
    int m0 = blockIdx.x * 64;

    // acc2[i][p]: row i (0..7), p: 0,1 = W0 col-pairs; 2,3 = W1 col-pairs
    unsigned long long acc2[8][4];
#pragma unroll
    for (int i = 0; i < 8; i++)
#pragma unroll
        for (int p = 0; p < 4; p++) acc2[i][p] = 0ull;

    for (int k0 = 0; k0 < DIN; k0 += 16) {
        // A tile: 64 rows x 16 k, duplicated-transposed into As2[k][m]
        {
            int row = tid >> 2;              // 0..63
            int kq  = (tid & 3) * 4;         // 0,4,8,12
            int gr  = m0 + row;
            float4 v = make_float4(0.f, 0.f, 0.f, 0.f);
            if (gr < N)
                v = *(const float4*)&X[(size_t)gr * DIN + k0 + kq];
            As2[kq + 0][row] = pack2(v.x);
            As2[kq + 1][row] = pack2(v.y);
            As2[kq + 2][row] = pack2(v.z);
            As2[kq + 3][row] = pack2(v.w);
        }
        // B tile: 16 k x 256 n  (n<128 from W0, else W1); 4 float4 / thread
        {
            int q  = tid & 63;               // quad index 0..63
            int kr = tid >> 6;               // 0..3
            int c4 = q * 4;
            const float* srcW = (c4 < 128) ? W0 : W1;
            int cc = (c4 < 128) ? c4 : c4 - 128;
#pragma unroll
            for (int h = 0; h < 4; h++) {
                int k = kr + h * 4;
                *(float4*)&Bs[k][c4] =
                    *(const float4*)&srcW[(size_t)(k0 + k) * DOUT + cc];
            }
        }
        __syncthreads();

#pragma unroll
        for (int kk = 0; kk < 16; kk++) {
            // a: 8 duplicated row values, warp-broadcast (ty uniform in warp)
            unsigned long long aa[8];
            ulonglong2 t0 = *(const ulonglong2*)&As2[kk][ty * 8 + 0];
            ulonglong2 t1 = *(const ulonglong2*)&As2[kk][ty * 8 + 2];
            ulonglong2 t2 = *(const ulonglong2*)&As2[kk][ty * 8 + 4];
            ulonglong2 t3 = *(const ulonglong2*)&As2[kk][ty * 8 + 6];
            aa[0] = t0.x; aa[1] = t0.y; aa[2] = t1.x; aa[3] = t1.y;
            aa[4] = t2.x; aa[5] = t2.y; aa[6] = t3.x; aa[7] = t3.y;
            // b: col-pairs straight from float4 SMEM (no packing)
            ulonglong2 bA = *(const ulonglong2*)&Bs[kk][tx * 4];
            ulonglong2 bB = *(const ulonglong2*)&Bs[kk][128 + tx * 4];
            unsigned long long bp[4] = { bA.x, bA.y, bB.x, bB.y };
#pragma unroll
            for (int i = 0; i < 8; i++)
#pragma unroll
                for (int p = 0; p < 4; p++)
                    ffma2(acc2[i][p], aa[i], bp[p]);
        }
        __syncthreads();
    }

    // Epilogue (tiles now dead; sred aliases them)
    float4 b0v = *(const float4*)&b0[tx * 4];
    float psum[4] = {0.f, 0.f, 0.f, 0.f};
    float psq[4]  = {0.f, 0.f, 0.f, 0.f};

#pragma unroll
    for (int i = 0; i < 8; i++) {
        int m = m0 + ty * 8 + i;
        if (m >= N) continue;
        // p0 half: relu + bias + stats
        float r0 = fmaxf(f2lo(acc2[i][0]), 0.f) + b0v.x;
        float r1 = fmaxf(f2hi(acc2[i][0]), 0.f) + b0v.y;
        float r2 = fmaxf(f2lo(acc2[i][1]), 0.f) + b0v.z;
        float r3 = fmaxf(f2hi(acc2[i][1]), 0.f) + b0v.w;
        *(float4*)&out[(size_t)m * (2 * DOUT) + tx * 4] =
            make_float4(r0, r1, r2, r3);
        psum[0] += r0; psq[0] = fmaf(r0, r0, psq[0]);
        psum[1] += r1; psq[1] = fmaf(r1, r1, psq[1]);
        psum[2] += r2; psq[2] = fmaf(r2, r2, psq[2]);
        psum[3] += r3; psq[3] = fmaf(r3, r3, psq[3]);
        // Y1 half: raw
        *(float4*)&g_y1[(size_t)m * DIN + tx * 4] =
            make_float4(f2lo(acc2[i][2]), f2hi(acc2[i][2]),
                        f2lo(acc2[i][3]), f2hi(acc2[i][3]));
    }

    // Stats: conflict-free shared staging (thread slot unique), then 1 pass
    *(float4*)&sred_s[ty][tx * 4] = make_float4(psum[0], psum[1], psum[2], psum[3]);
    *(float4*)&sred_q[ty][tx * 4] = make_float4(psq[0], psq[1], psq[2], psq[3]);
    __syncthreads();
    if (tid < 128) {
        float s = 0.f, q = 0.f;
#pragma unroll
        for (int w = 0; w < 8; w++) { s += sred_s[w][tid]; q += sred_q[w][tid]; }
        atomicAdd(&g_stats[tid], s);
        atomicAdd(&g_stats[256 + tid], q);
    }
}

// ---------------------------------------------------------------------------
// Fused SpMM: p1[n] = relu(sum_e val*Y1[col]) + b1 -> out[:,128:256].
// One warp per node, lane owns a float4. 4-edge unroll.
__global__ __launch_bounds__(256)
void spmm_fused_kernel(const float* __restrict__ vals,
                       const int*   __restrict__ cols,
                       const float* __restrict__ b1,
                       float* __restrict__ out,
                       int N) {
    int warp = (blockIdx.x * blockDim.x + threadIdx.x) >> 5;
    int lane = threadIdx.x & 31;
    if (warp >= N) return;
    int s = g_rowptr[warp];
    int e = g_rowptr[warp + 1];
    float4 acc0 = make_float4(0.f, 0.f, 0.f, 0.f);
    float4 acc1 = make_float4(0.f, 0.f, 0.f, 0.f);
    int t = s;
    for (; t + 3 < e; t += 4) {
        float v0 = __ldg(&vals[t]),     v1 = __ldg(&vals[t + 1]);
        float v2 = __ldg(&vals[t + 2]), v3 = __ldg(&vals[t + 3]);
        int c0 = __ldg(&cols[t]),     c1 = __ldg(&cols[t + 1]);
        int c2 = __ldg(&cols[t + 2]), c3 = __ldg(&cols[t + 3]);
        float4 x0 = __ldg(&((const float4*)&g_y1[(size_t)c0 * DIN])[lane]);
        float4 x1 = __ldg(&((const float4*)&g_y1[(size_t)c1 * DIN])[lane]);
        float4 x2 = __ldg(&((const float4*)&g_y1[(size_t)c2 * DIN])[lane]);
        float4 x3 = __ldg(&((const float4*)&g_y1[(size_t)c3 * DIN])[lane]);
        acc0.x = fmaf(v0, x0.x, acc0.x); acc0.y = fmaf(v0, x0.y, acc0.y);
        acc0.z = fmaf(v0, x0.z, acc0.z); acc0.w = fmaf(v0, x0.w, acc0.w);
        acc1.x = fmaf(v1, x1.x, acc1.x); acc1.y = fmaf(v1, x1.y, acc1.y);
        acc1.z = fmaf(v1, x1.z, acc1.z); acc1.w = fmaf(v1, x1.w, acc1.w);
        acc0.x = fmaf(v2, x2.x, acc0.x); acc0.y = fmaf(v2, x2.y, acc0.y);
        acc0.z = fmaf(v2, x2.z, acc0.z); acc0.w = fmaf(v2, x2.w, acc0.w);
        acc1.x = fmaf(v3, x3.x, acc1.x); acc1.y = fmaf(v3, x3.y, acc1.y);
        acc1.z = fmaf(v3, x3.z, acc1.z); acc1.w = fmaf(v3, x3.w, acc1.w);
    }
    for (; t < e; t++) {
        float v0 = __ldg(&vals[t]);
        int   c0 = __ldg(&cols[t]);
        float4 x0 = __ldg(&((const float4*)&g_y1[(size_t)c0 * DIN])[lane]);
        acc0.x = fmaf(v0, x0.x, acc0.x); acc0.y = fmaf(v0, x0.y, acc0.y);
        acc0.z = fmaf(v0, x0.z, acc0.z); acc0.w = fmaf(v0, x0.w, acc0.w);
    }
    float4 bb = __ldg(&((const float4*)b1)[lane]);
    float4 r;
    r.x = fmaxf(acc0.x + acc1.x, 0.f) + bb.x;
    r.y = fmaxf(acc0.y + acc1.y, 0.f) + bb.y;
    r.z = fmaxf(acc0.z + acc1.z, 0.f) + bb.z;
    r.w = fmaxf(acc0.w + acc1.w, 0.f) + bb.w;
    *(float4*)&out[(size_t)warp * (2 * DOUT) + DOUT + lane * 4] = r;
}

// ---------------------------------------------------------------------------
// Column sum/sumsq over out[:,128:256] (L2-resident, just written by spmm).
__global__ void p1_stats_kernel(const float* __restrict__ out, int N) {
    __shared__ float ss[256], sq[256];
    int tid = threadIdx.x;
    int c   = tid & 127;
    int rh  = tid >> 7;
    int chunk = (N + gridDim.x - 1) / gridDim.x;
    int r0 = blockIdx.x * chunk;
    int r1 = r0 + chunk; if (r1 > N) r1 = N;
    float s = 0.f, q = 0.f;
    for (int r = r0 + rh; r < r1; r += 2) {
        float v = __ldg(&out[(size_t)r * (2 * DOUT) + DOUT + c]);
        s += v;
        q = fmaf(v, v, q);
    }
    ss[tid] = s; sq[tid] = q;
    __syncthreads();
    if (tid < 128) {
        s = ss[tid] + ss[tid + 128];
        q = sq[tid] + sq[tid + 128];
        atomicAdd(&g_stats[128 + tid], s);
        atomicAdd(&g_stats[384 + tid], q);
    }
}

// ---------------------------------------------------------------------------
__global__ void bn_finalize_half_kernel(const float* __restrict__ gamma,
                                        const float* __restrict__ beta,
                                        int N, int base) {
    int c = base + threadIdx.x;             // 128 threads
    float inv_n = 1.0f / (float)N;
    float mean = g_stats[c] * inv_n;
    float var  = g_stats[256 + c] * inv_n - mean * mean;
    float s = gamma[c] * rsqrtf(var + BN_EPS);
    g_stats[512 + c] = s;
    g_stats[768 + c] = beta[c] - mean * s;
}

// Normalize one 128-col half of out. half=0 -> cols 0..127, half=1 -> 128..255.
__global__ void bn_apply_half_kernel(float* __restrict__ out, int N, int half) {
    size_t total = (size_t)N * 32;          // float4s in this half
    size_t i = (size_t)blockIdx.x * blockDim.x + threadIdx.x;
    size_t stride = (size_t)gridDim.x * blockDim.x;
    const float4* scale4 = (const float4*)&g_stats[512];
    const float4* shift4 = (const float4*)&g_stats[768];
    for (; i < total; i += stride) {
        size_t row = i >> 5;
        int    q   = (int)(i & 31);
        int    c4  = half * 32 + q;
        float4 s  = scale4[c4];
        float4 sh = shift4[c4];
        size_t idx = row * 64 + c4;
        float4 v = ((float4*)out)[idx];
        v.x = fmaf(v.x, s.x, sh.x);
        v.y = fmaf(v.y, s.y, sh.y);
        v.z = fmaf(v.z, s.z, sh.z);
        v.w = fmaf(v.w, s.w, sh.w);
        ((float4*)out)[idx] = v;
    }
}

// ---------------------------------------------------------------------------
extern "C" void kernel_launch(void* const* d_in, const int* in_sizes, int n_in,
                              void* d_out, int out_size) {
    const float* feat     = (const float*)d_in[0];
    const float* adj_vals = (const float*)d_in[1];
    const float* W0       = (const float*)d_in[2];
    const float* W1       = (const float*)d_in[3];
    const float* b0       = (const float*)d_in[4];
    const float* b1       = (const float*)d_in[5];
    const float* gamma    = (const float*)d_in[6];
    const float* beta     = (const float*)d_in[7];
    const int*   adj_rows = (const int*)d_in[8];
    const int*   adj_cols = (const int*)d_in[9];
    float* out = (float*)d_out;

    int N = in_sizes[0] / DIN;
    int E = in_sizes[1];

    // Side stream + events, created once on the eager correctness call
    // (before graph capture), reused inside capture via event fork/join.
    static cudaStream_t s1 = nullptr;
    static cudaEvent_t  eZ = nullptr, eR = nullptr, eD = nullptr, eA0 = nullptr;
    if (s1 == nullptr) {
        cudaStreamCreateWithFlags(&s1, cudaStreamNonBlocking);
        cudaEventCreateWithFlags(&eZ,  cudaEventDisableTiming);
        cudaEventCreateWithFlags(&eR,  cudaEventDisableTiming);
        cudaEventCreateWithFlags(&eD,  cudaEventDisableTiming);
        cudaEventCreateWithFlags(&eA0, cudaEventDisableTiming);
    }

    int gblocks = (N + 63) / 64;
    int sblocks = (N * 32 + 255) / 256;
    int ablocks = (N * 32 + 255) / 256;
    if (ablocks > 8192) ablocks = 8192;

    // main: zero stats, then FORK
    zero_stats_kernel<<<1, 512>>>();
    cudaEventRecord(eZ, 0);

    // side (forked): rowptr overlaps dgemm
    cudaStreamWaitEvent(s1, eZ, 0);
    build_rowptr_kernel<<<(E + 255) / 256, 256, 0, s1>>>(adj_rows, E, N);
    cudaEventRecord(eR, s1);

    // main: dgemm
    dgemm_kernel<<<gblocks, 256>>>(feat, W0, W1, b0, out, N);
    cudaEventRecord(eD, 0);

    // side: p0's BN half runs during spmm (tiny kernels, can co-reside)
    cudaStreamWaitEvent(s1, eD, 0);
    bn_finalize_half_kernel<<<1, 128, 0, s1>>>(gamma, beta, N, 0);
    bn_apply_half_kernel<<<ablocks, 256, 0, s1>>>(out, N, 0);
    cudaEventRecord(eA0, s1);

    // main: spmm (needs rowptr + Y1) -> p1 stats -> p1 BN half
    cudaStreamWaitEvent(0, eR, 0);
    spmm_fused_kernel<<<sblocks, 256>>>(adj_vals, adj_cols, b1, out, N);
    p1_stats_kernel<<<256, 256>>>(out, N);
    bn_finalize_half_kernel<<<1, 128>>>(gamma, beta, N, 128);
    bn_apply_half_kernel<<<ablocks, 256>>>(out, N, 1);

    // join side branch before capture ends
    cudaStreamWaitEvent(0, eA0, 0);
}

// round 12
// speedup vs baseline: 1.2152x; 1.0684x over previous
#include <cuda_runtime.h>
#include <cuda_bf16.h>
#include <cstdint>

#define DIN   128
#define DOUT  128
#define MAXN  100000
#define BN_EPS 1e-5f

// Scratch (allocation-free rule: __device__ globals)
__device__ float g_y1[(size_t)MAXN * DIN];     // Y1 = feat @ W1  [N,128]
__device__ int   g_rowptr[MAXN + 1];
// [0..255]=colsum, [256..511]=colsumsq
__device__ float g_stats[512];

// ---------------------------------------------------------------------------
__device__ __forceinline__ void ffma2(unsigned long long& d,
                                      unsigned long long a,
                                      unsigned long long b) {
    asm("fma.rn.f32x2 %0, %1, %2, %3;" : "=l"(d) : "l"(a), "l"(b), "l"(d));
}
__device__ __forceinline__ unsigned long long pack2(float x) {
    unsigned long long r;
    unsigned int u = __float_as_uint(x);
    asm("mov.b64 %0, {%1, %1};" : "=l"(r) : "r"(u));
    return r;
}
__device__ __forceinline__ float f2lo(unsigned long long x) {
    return __uint_as_float((unsigned int)(x & 0xFFFFFFFFull));
}
__device__ __forceinline__ float f2hi(unsigned long long x) {
    return __uint_as_float((unsigned int)(x >> 32));
}

// ---------------------------------------------------------------------------
__global__ void zero_stats_kernel() {
    g_stats[threadIdx.x] = 0.0f;          // 512 threads
}

// adj_rows is sorted; scatter row boundaries into CSR row_ptr.
__global__ void build_rowptr_kernel(const int* __restrict__ rows, int E, int N) {
    int e = blockIdx.x * blockDim.x + threadIdx.x;
    if (e >= E) return;
    int r = rows[e];
    int prev = (e == 0) ? -1 : rows[e - 1];
    for (int rr = prev + 1; rr <= r; rr++) g_rowptr[rr] = e;
    if (e == E - 1) {
        for (int rr = r + 1; rr <= N; rr++) g_rowptr[rr] = E;
    }
}

// ---------------------------------------------------------------------------
// Double-GEMM, M=64 x N=256 tile, 256 threads, 2 CTAs/SM.
//   p0 = relu(feat@W0)+b0  -> out[:,0:128]  (+ BN column stats)
//   Y1 = feat@W1           -> g_y1          (raw; SpMM consumes it)
// ROW-paired FFMA2 accumulators: a-pairs free from As float4 LDS (2xLDS.128),
// b duplicated via pack2 MOVs that dual-issue into FFMA2 rt=2 gaps.
// Per thread-kk: 4 LDS.128 (64B) + 8 MOV + 32 FFMA2 -> FFMA2-pipe-bound.
// SMEM (~20.7KB/CTA): As float[16][68] | Bs float[16][256];
// sred_{s,q} (8KB) alias the tile region (tiles dead before epilogue).
__global__ __launch_bounds__(256, 2)
void dgemm_kernel(const float* __restrict__ X,
                  const float* __restrict__ W0,
                  const float* __restrict__ W1,
                  const float* __restrict__ b0,
                  float* __restrict__ out,
                  int N) {
    __shared__ __align__(16) char smem_raw[16 * 68 * 4 + 16 * 256 * 4];
    float (*As)[68]  = (float (*)[68])smem_raw;
    float (*Bs)[256] = (float (*)[256])(smem_raw + 16 * 68 * 4);
    float (*sred_s)[128] = (float (*)[128])smem_raw;
    float (*sred_q)[128] = (float (*)[128])(smem_raw + 4096);

    int tid = threadIdx.x;
    int tx = tid & 31;                  // lane: 8 cols (4 W0-cols + 4 W1-cols)
    int ty = tid >> 5;                  // warp: 8 rows
    int m0 = blockIdx.x * 64;

    // acc2[p][j]: row-pair p (rows ty*8+2p, +1), j: 0..3 W0 cols, 4..7 W1 cols
    unsigned long long acc2[4][8];
#pragma unroll
    for (int p = 0; p < 4; p++)
#pragma unroll
        for (int j = 0; j < 8; j++) acc2[p][j] = 0ull;

    for (int k0 = 0; k0 < DIN; k0 += 16) {
        // A tile: 64 rows x 16 k, transposed into As[k][m] (plain floats)
        {
            int row = tid >> 2;              // 0..63
            int kq  = (tid & 3) * 4;         // 0,4,8,12
            int gr  = m0 + row;
            float4 v = make_float4(0.f, 0.f, 0.f, 0.f);
            if (gr < N)
                v = *(const float4*)&X[(size_t)gr * DIN + k0 + kq];
            As[kq + 0][row] = v.x;
            As[kq + 1][row] = v.y;
            As[kq + 2][row] = v.z;
            As[kq + 3][row] = v.w;
        }
        // B tile: 16 k x 256 n  (n<128 from W0, else W1); 4 float4 / thread
        {
            int q  = tid & 63;               // quad index 0..63
            int kr = tid >> 6;               // 0..3
            int c4 = q * 4;
            const float* srcW = (c4 < 128) ? W0 : W1;
            int cc = (c4 < 128) ? c4 : c4 - 128;
#pragma unroll
            for (int h = 0; h < 4; h++) {
                int k = kr + h * 4;
                *(float4*)&Bs[k][c4] =
                    *(const float4*)&srcW[(size_t)(k0 + k) * DOUT + cc];
            }
        }
        __syncthreads();

#pragma unroll
        for (int kk = 0; kk < 16; kk++) {
            // a: 8 row values as 4 u64 pairs (broadcast float4 reads)
            ulonglong2 a01 = *(const ulonglong2*)&As[kk][ty * 8];
            ulonglong2 a23 = *(const ulonglong2*)&As[kk][ty * 8 + 4];
            unsigned long long ap[4] = { a01.x, a01.y, a23.x, a23.y };
            // b: 8 scalar cols, duplicated
            float4 bA = *(const float4*)&Bs[kk][tx * 4];
            float4 bB = *(const float4*)&Bs[kk][128 + tx * 4];
            unsigned long long bd[8] = {
                pack2(bA.x), pack2(bA.y), pack2(bA.z), pack2(bA.w),
                pack2(bB.x), pack2(bB.y), pack2(bB.z), pack2(bB.w)
            };
#pragma unroll
            for (int p = 0; p < 4; p++)
#pragma unroll
                for (int j = 0; j < 8; j++)
                    ffma2(acc2[p][j], ap[p], bd[j]);
        }
        __syncthreads();
    }

    // Epilogue (tiles dead; sred aliases them)
    float4 b0v = *(const float4*)&b0[tx * 4];
    float psum[4] = {0.f, 0.f, 0.f, 0.f};
    float psq[4]  = {0.f, 0.f, 0.f, 0.f};

#pragma unroll
    for (int p = 0; p < 4; p++) {
#pragma unroll
        for (int half = 0; half < 2; half++) {
            int m = m0 + ty * 8 + 2 * p + half;
            if (m >= N) continue;
            float v0 = half ? f2hi(acc2[p][0]) : f2lo(acc2[p][0]);
            float v1 = half ? f2hi(acc2[p][1]) : f2lo(acc2[p][1]);
            float v2 = half ? f2hi(acc2[p][2]) : f2lo(acc2[p][2]);
            float v3 = half ? f2hi(acc2[p][3]) : f2lo(acc2[p][3]);
            float r0 = fmaxf(v0, 0.f) + b0v.x;
            float r1 = fmaxf(v1, 0.f) + b0v.y;
            float r2 = fmaxf(v2, 0.f) + b0v.z;
            float r3 = fmaxf(v3, 0.f) + b0v.w;
            *(float4*)&out[(size_t)m * (2 * DOUT) + tx * 4] =
                make_float4(r0, r1, r2, r3);
            psum[0] += r0; psq[0] = fmaf(r0, r0, psq[0]);
            psum[1] += r1; psq[1] = fmaf(r1, r1, psq[1]);
            psum[2] += r2; psq[2] = fmaf(r2, r2, psq[2]);
            psum[3] += r3; psq[3] = fmaf(r3, r3, psq[3]);
            float y0 = half ? f2hi(acc2[p][4]) : f2lo(acc2[p][4]);
            float y1 = half ? f2hi(acc2[p][5]) : f2lo(acc2[p][5]);
            float y2 = half ? f2hi(acc2[p][6]) : f2lo(acc2[p][6]);
            float y3 = half ? f2hi(acc2[p][7]) : f2lo(acc2[p][7]);
            *(float4*)&g_y1[(size_t)m * DIN + tx * 4] =
                make_float4(y0, y1, y2, y3);
        }
    }

    // Stats: conflict-free shared staging, then one atomic pass
    *(float4*)&sred_s[ty][tx * 4] = make_float4(psum[0], psum[1], psum[2], psum[3]);
    *(float4*)&sred_q[ty][tx * 4] = make_float4(psq[0], psq[1], psq[2], psq[3]);
    __syncthreads();
    if (tid < 128) {
        float s = 0.f, q = 0.f;
#pragma unroll
        for (int w = 0; w < 8; w++) { s += sred_s[w][tid]; q += sred_q[w][tid]; }
        atomicAdd(&g_stats[tid], s);
        atomicAdd(&g_stats[256 + tid], q);
    }
}

// ---------------------------------------------------------------------------
// Fused SpMM: p1[n] = relu(sum_e val*Y1[col]) + b1 -> out[:,128:256],
// with p1 BN column stats fused in (smem reduction + global atomics).
// One warp per node, lane owns a float4. 4-edge unroll.
__global__ __launch_bounds__(256)
void spmm_fused_kernel(const float* __restrict__ vals,
                       const int*   __restrict__ cols,
                       const float* __restrict__ b1,
                       float* __restrict__ out,
                       int N) {
    __shared__ float s_sum[128], s_sq[128];
    int tid  = threadIdx.x;
    int warp = (blockIdx.x * blockDim.x + tid) >> 5;
    int lane = tid & 31;
    if (tid < 128) { s_sum[tid] = 0.f; s_sq[tid] = 0.f; }
    __syncthreads();

    if (warp < N) {
        int s = g_rowptr[warp];
        int e = g_rowptr[warp + 1];
        float4 acc0 = make_float4(0.f, 0.f, 0.f, 0.f);
        float4 acc1 = make_float4(0.f, 0.f, 0.f, 0.f);
        int t = s;
        for (; t + 3 < e; t += 4) {
            float v0 = __ldg(&vals[t]),     v1 = __ldg(&vals[t + 1]);
            float v2 = __ldg(&vals[t + 2]), v3 = __ldg(&vals[t + 3]);
            int c0 = __ldg(&cols[t]),     c1 = __ldg(&cols[t + 1]);
            int c2 = __ldg(&cols[t + 2]), c3 = __ldg(&cols[t + 3]);
            float4 x0 = __ldg(&((const float4*)&g_y1[(size_t)c0 * DIN])[lane]);
            float4 x1 = __ldg(&((const float4*)&g_y1[(size_t)c1 * DIN])[lane]);
            float4 x2 = __ldg(&((const float4*)&g_y1[(size_t)c2 * DIN])[lane]);
            float4 x3 = __ldg(&((const float4*)&g_y1[(size_t)c3 * DIN])[lane]);
            acc0.x = fmaf(v0, x0.x, acc0.x); acc0.y = fmaf(v0, x0.y, acc0.y);
            acc0.z = fmaf(v0, x0.z, acc0.z); acc0.w = fmaf(v0, x0.w, acc0.w);
            acc1.x = fmaf(v1, x1.x, acc1.x); acc1.y = fmaf(v1, x1.y, acc1.y);
            acc1.z = fmaf(v1, x1.z, acc1.z); acc1.w = fmaf(v1, x1.w, acc1.w);
            acc0.x = fmaf(v2, x2.x, acc0.x); acc0.y = fmaf(v2, x2.y, acc0.y);
            acc0.z = fmaf(v2, x2.z, acc0.z); acc0.w = fmaf(v2, x2.w, acc0.w);
            acc1.x = fmaf(v3, x3.x, acc1.x); acc1.y = fmaf(v3, x3.y, acc1.y);
            acc1.z = fmaf(v3, x3.z, acc1.z); acc1.w = fmaf(v3, x3.w, acc1.w);
        }
        for (; t < e; t++) {
            float v0 = __ldg(&vals[t]);
            int   c0 = __ldg(&cols[t]);
            float4 x0 = __ldg(&((const float4*)&g_y1[(size_t)c0 * DIN])[lane]);
            acc0.x = fmaf(v0, x0.x, acc0.x); acc0.y = fmaf(v0, x0.y, acc0.y);
            acc0.z = fmaf(v0, x0.z, acc0.z); acc0.w = fmaf(v0, x0.w, acc0.w);
        }
        float4 bb = __ldg(&((const float4*)b1)[lane]);
        float4 r;
        r.x = fmaxf(acc0.x + acc1.x, 0.f) + bb.x;
        r.y = fmaxf(acc0.y + acc1.y, 0.f) + bb.y;
        r.z = fmaxf(acc0.z + acc1.z, 0.f) + bb.z;
        r.w = fmaxf(acc0.w + acc1.w, 0.f) + bb.w;
        *(float4*)&out[(size_t)warp * (2 * DOUT) + DOUT + lane * 4] = r;
        // stats into smem (spread addresses; ~2 cyc/lane)
        atomicAdd(&s_sum[lane * 4 + 0], r.x);
        atomicAdd(&s_sum[lane * 4 + 1], r.y);
        atomicAdd(&s_sum[lane * 4 + 2], r.z);
        atomicAdd(&s_sum[lane * 4 + 3], r.w);
        atomicAdd(&s_sq[lane * 4 + 0], r.x * r.x);
        atomicAdd(&s_sq[lane * 4 + 1], r.y * r.y);
        atomicAdd(&s_sq[lane * 4 + 2], r.z * r.z);
        atomicAdd(&s_sq[lane * 4 + 3], r.w * r.w);
    }
    __syncthreads();
    if (tid < 128) {
        atomicAdd(&g_stats[128 + tid], s_sum[tid]);
        atomicAdd(&g_stats[384 + tid], s_sq[tid]);
    }
}

// ---------------------------------------------------------------------------
// Normalize one 128-col half of out; BN finalize inlined in the prologue.
// half=0 -> cols 0..127, half=1 -> cols 128..255.
__global__ __launch_bounds__(256)
void bn_apply_half_kernel(float* __restrict__ out,
                          const float* __restrict__ gamma,
                          const float* __restrict__ beta,
                          int N, int half) {
    __shared__ float scale[128], shift[128];
    int tid = threadIdx.x;
    if (tid < 128) {
        int c = half * 128 + tid;
        float inv_n = 1.0f / (float)N;
        float mean = g_stats[c] * inv_n;
        float var  = g_stats[256 + c] * inv_n - mean * mean;
        float s = __ldg(&gamma[c]) * rsqrtf(var + BN_EPS);
        scale[tid] = s;
        shift[tid] = __ldg(&beta[c]) - mean * s;
    }
    __syncthreads();

    size_t total = (size_t)N * 32;          // float4s in this half
    size_t i = (size_t)blockIdx.x * blockDim.x + tid;
    size_t stride = (size_t)gridDim.x * blockDim.x;
    const float4* scale4 = (const float4*)scale;
    const float4* shift4 = (const float4*)shift;
    for (; i < total; i += stride) {
        size_t row = i >> 5;
        int    q   = (int)(i & 31);
        float4 s  = scale4[q];
        float4 sh = shift4[q];
        size_t idx = row * 64 + half * 32 + q;
        float4 v = ((float4*)out)[idx];
        v.x = fmaf(v.x, s.x, sh.x);
        v.y = fmaf(v.y, s.y, sh.y);
        v.z = fmaf(v.z, s.z, sh.z);
        v.w = fmaf(v.w, s.w, sh.w);
        ((float4*)out)[idx] = v;
    }
}

// ---------------------------------------------------------------------------
extern "C" void kernel_launch(void* const* d_in, const int* in_sizes, int n_in,
                              void* d_out, int out_size) {
    const float* feat     = (const float*)d_in[0];
    const float* adj_vals = (const float*)d_in[1];
    const float* W0       = (const float*)d_in[2];
    const float* W1       = (const float*)d_in[3];
    const float* b0       = (const float*)d_in[4];
    const float* b1       = (const float*)d_in[5];
    const float* gamma    = (const float*)d_in[6];
    const float* beta     = (const float*)d_in[7];
    const int*   adj_rows = (const int*)d_in[8];
    const int*   adj_cols = (const int*)d_in[9];
    float* out = (float*)d_out;

    int N = in_sizes[0] / DIN;
    int E = in_sizes[1];

    // Side stream + events, created once on the eager correctness call
    // (before graph capture), reused inside capture via event fork/join.
    static cudaStream_t s1 = nullptr;
    static cudaEvent_t  eZ = nullptr, eR = nullptr, eD = nullptr, eA0 = nullptr;
    if (s1 == nullptr) {
        cudaStreamCreateWithFlags(&s1, cudaStreamNonBlocking);
        cudaEventCreateWithFlags(&eZ,  cudaEventDisableTiming);
        cudaEventCreateWithFlags(&eR,  cudaEventDisableTiming);
        cudaEventCreateWithFlags(&eD,  cudaEventDisableTiming);
        cudaEventCreateWithFlags(&eA0, cudaEventDisableTiming);
    }

    int gblocks = (N + 63) / 64;
    int sblocks = (N * 32 + 255) / 256;
    int ablocks = (N * 32 + 255) / 256;
    if (ablocks > 8192) ablocks = 8192;

    // main: zero stats, then FORK
    zero_stats_kernel<<<1, 512>>>();
    cudaEventRecord(eZ, 0);

    // side (forked): rowptr overlaps dgemm
    cudaStreamWaitEvent(s1, eZ, 0);
    build_rowptr_kernel<<<(E + 255) / 256, 256, 0, s1>>>(adj_rows, E, N);
    cudaEventRecord(eR, s1);

    // main: dgemm
    dgemm_kernel<<<gblocks, 256>>>(feat, W0, W1, b0, out, N);
    cudaEventRecord(eD, 0);

    // side: p0's BN half (finalize inlined) runs during spmm
    cudaStreamWaitEvent(s1, eD, 0);
    bn_apply_half_kernel<<<ablocks, 256, 0, s1>>>(out, gamma, beta, N, 0);
    cudaEventRecord(eA0, s1);

    // main: spmm (needs rowptr + Y1; stats fused) -> p1 BN half
    cudaStreamWaitEvent(0, eR, 0);
    spmm_fused_kernel<<<sblocks, 256>>>(adj_vals, adj_cols, b1, out, N);
    bn_apply_half_kernel<<<ablocks, 256>>>(out, gamma, beta, N, 1);

    // join side branch before capture ends
    cudaStreamWaitEvent(0, eA0, 0);
}

// round 13
// speedup vs baseline: 1.2686x; 1.0440x over previous
#include <cuda_runtime.h>
#include <cuda_bf16.h>
#include <cstdint>

#define DIN   128
#define DOUT  128
#define MAXN  100000
#define BN_EPS 1e-5f

// Scratch (allocation-free rule: __device__ globals)
__device__ float g_y1[(size_t)MAXN * DIN];     // Y1 = feat @ W1  [N,128]
__device__ int   g_rowptr[MAXN + 1];
// [0..255]=colsum, [256..511]=colsumsq
__device__ float g_stats[512];

// ---------------------------------------------------------------------------
__device__ __forceinline__ void ffma2(unsigned long long& d,
                                      unsigned long long a,
                                      unsigned long long b) {
    asm("fma.rn.f32x2 %0, %1, %2, %3;" : "=l"(d) : "l"(a), "l"(b), "l"(d));
}
__device__ __forceinline__ unsigned long long pack2(float x) {
    unsigned long long r;
    unsigned int u = __float_as_uint(x);
    asm("mov.b64 %0, {%1, %1};" : "=l"(r) : "r"(u));
    return r;
}
__device__ __forceinline__ float f2lo(unsigned long long x) {
    return __uint_as_float((unsigned int)(x & 0xFFFFFFFFull));
}
__device__ __forceinline__ float f2hi(unsigned long long x) {
    return __uint_as_float((unsigned int)(x >> 32));
}
__device__ __forceinline__ uint32_t smem_u32(const void* p) {
    return (uint32_t)__cvta_generic_to_shared(p);
}
__device__ __forceinline__ void cp16(uint32_t dst, const void* src) {
    asm volatile("cp.async.cg.shared.global [%0], [%1], 16;"
                 :: "r"(dst), "l"(src));
}
#define CP_COMMIT() asm volatile("cp.async.commit_group;" ::: "memory")
#define CP_WAIT1()  asm volatile("cp.async.wait_group 1;" ::: "memory")
#define CP_WAIT0()  asm volatile("cp.async.wait_group 0;" ::: "memory")

// ---------------------------------------------------------------------------
__global__ void zero_stats_kernel() {
    g_stats[threadIdx.x] = 0.0f;          // 512 threads
}

// adj_rows is sorted; scatter row boundaries into CSR row_ptr.
__global__ void build_rowptr_kernel(const int* __restrict__ rows, int E, int N) {
    int e = blockIdx.x * blockDim.x + threadIdx.x;
    if (e >= E) return;
    int r = rows[e];
    int prev = (e == 0) ? -1 : rows[e - 1];
    for (int rr = prev + 1; rr <= r; rr++) g_rowptr[rr] = e;
    if (e == E - 1) {
        for (int rr = r + 1; rr <= N; rr++) g_rowptr[rr] = E;
    }
}

// ---------------------------------------------------------------------------
// Double-GEMM, M=64 x N=256 tile, 256 threads, 2 CTAs/SM, cp.async
// double-buffered tiles (loads fully hidden; 2 barriers/iter, zero exposure).
//   p0 = relu(feat@W0)+b0  -> out[:,0:128]  (+ BN column stats)
//   Y1 = feat@W1           -> g_y1          (raw; SpMM consumes it)
// ROW-paired FFMA2 accumulators (a-pairs free from As float4 LDS).
// SMEM 41.5KB/CTA: As[2][16][68] | Bs[2][16][256]; sred aliases tiles.
__global__ __launch_bounds__(256, 2)
void dgemm_kernel(const float* __restrict__ X,
                  const float* __restrict__ W0,
                  const float* __restrict__ W1,
                  const float* __restrict__ b0,
                  float* __restrict__ out,
                  int N) {
    __shared__ __align__(16) char smem_raw[2 * 16 * 68 * 4 + 2 * 16 * 256 * 4];
    float (*As)[16][68]  = (float (*)[16][68])smem_raw;
    float (*Bs)[16][256] = (float (*)[16][256])(smem_raw + 2 * 16 * 68 * 4);
    float (*sred_s)[128] = (float (*)[128])smem_raw;
    float (*sred_q)[128] = (float (*)[128])(smem_raw + 4096);

    int tid = threadIdx.x;
    int tx = tid & 31;                  // lane: 8 cols (4 W0-cols + 4 W1-cols)
    int ty = tid >> 5;                  // warp: 8 rows
    int m0 = blockIdx.x * 64;

    // A-load role: one float4 (16B) per k0 chunk, transposed on store
    int arow = tid >> 2;                // 0..63
    int akq  = (tid & 3) * 4;           // 0,4,8,12
    int agr  = m0 + arow;
    bool avalid = agr < N;
    const float* aptr = X + (size_t)agr * DIN + akq;   // +16*i per chunk

    // B-load role: 4 x 16B per k0 chunk
    int bq  = tid & 63;
    int bkr = tid >> 6;                 // 0..3
    int bc4 = bq * 4;
    const float* bw = (bc4 < 128) ? W0 : W1;
    int bcc = (bc4 < 128) ? bc4 : bc4 - 128;

    // acc2[p][j]: row-pair p (rows ty*8+2p, +1), j: 0..3 W0 cols, 4..7 W1 cols
    unsigned long long acc2[4][8];
#pragma unroll
    for (int p = 0; p < 4; p++)
#pragma unroll
        for (int j = 0; j < 8; j++) acc2[p][j] = 0ull;

    // ---- prologue: A(0) direct; B(0), B(1) via cp.async -------------------
    {
        float4 a0 = make_float4(0.f, 0.f, 0.f, 0.f);
        if (avalid) a0 = *(const float4*)aptr;
        As[0][akq + 0][arow] = a0.x;
        As[0][akq + 1][arow] = a0.y;
        As[0][akq + 2][arow] = a0.z;
        As[0][akq + 3][arow] = a0.w;
    }
#pragma unroll
    for (int h = 0; h < 4; h++) {
        int k = bkr + h * 4;
        cp16(smem_u32(&Bs[0][k][bc4]), &bw[(size_t)k * DOUT + bcc]);
    }
    CP_COMMIT();
#pragma unroll
    for (int h = 0; h < 4; h++) {
        int k = bkr + h * 4;
        cp16(smem_u32(&Bs[1][k][bc4]), &bw[(size_t)(16 + k) * DOUT + bcc]);
    }
    CP_COMMIT();

    // ---- pipelined main loop (8 chunks of BK=16) --------------------------
#pragma unroll
    for (int i = 0; i < 8; i++) {
        int b = i & 1;
        if (i < 6) { CP_WAIT1(); } else { CP_WAIT0(); }
        __syncthreads();                 // Bs[b] + As[b] ready for all

        // prefetch A(i+1) into regs (latency hidden behind compute)
        float4 an = make_float4(0.f, 0.f, 0.f, 0.f);
        if (i + 1 < 8 && avalid)
            an = *(const float4*)(aptr + (i + 1) * 16);

#pragma unroll
        for (int kk = 0; kk < 16; kk++) {
            ulonglong2 a01 = *(const ulonglong2*)&As[b][kk][ty * 8];
            ulonglong2 a23 = *(const ulonglong2*)&As[b][kk][ty * 8 + 4];
            unsigned long long ap[4] = { a01.x, a01.y, a23.x, a23.y };
            float4 bA = *(const float4*)&Bs[b][kk][tx * 4];
            float4 bB = *(const float4*)&Bs[b][kk][128 + tx * 4];
            unsigned long long bd[8] = {
                pack2(bA.x), pack2(bA.y), pack2(bA.z), pack2(bA.w),
                pack2(bB.x), pack2(bB.y), pack2(bB.z), pack2(bB.w)
            };
#pragma unroll
            for (int p = 0; p < 4; p++)
#pragma unroll
                for (int j = 0; j < 8; j++)
                    ffma2(acc2[p][j], ap[p], bd[j]);
        }

        // store A(i+1) into the other buffer (safe: all warps past this
        // iter's first barrier => compute(i-1) on that buffer is done)
        if (i + 1 < 8) {
            As[b ^ 1][akq + 0][arow] = an.x;
            As[b ^ 1][akq + 1][arow] = an.y;
            As[b ^ 1][akq + 2][arow] = an.z;
            As[b ^ 1][akq + 3][arow] = an.w;
        }
        __syncthreads();                 // all done reading Bs[b]/As tiles

        if (i + 2 < 8) {
#pragma unroll
            for (int h = 0; h < 4; h++) {
                int k = bkr + h * 4;
                cp16(smem_u32(&Bs[b][k][bc4]),
                     &bw[(size_t)((i + 2) * 16 + k) * DOUT + bcc]);
            }
            CP_COMMIT();
        }
    }

    // Epilogue (tiles dead; sred aliases them)
    float4 b0v = *(const float4*)&b0[tx * 4];
    float psum[4] = {0.f, 0.f, 0.f, 0.f};
    float psq[4]  = {0.f, 0.f, 0.f, 0.f};

#pragma unroll
    for (int p = 0; p < 4; p++) {
#pragma unroll
        for (int half = 0; half < 2; half++) {
            int m = m0 + ty * 8 + 2 * p + half;
            if (m >= N) continue;
            float v0 = half ? f2hi(acc2[p][0]) : f2lo(acc2[p][0]);
            float v1 = half ? f2hi(acc2[p][1]) : f2lo(acc2[p][1]);
            float v2 = half ? f2hi(acc2[p][2]) : f2lo(acc2[p][2]);
            float v3 = half ? f2hi(acc2[p][3]) : f2lo(acc2[p][3]);
            float r0 = fmaxf(v0, 0.f) + b0v.x;
            float r1 = fmaxf(v1, 0.f) + b0v.y;
            float r2 = fmaxf(v2, 0.f) + b0v.z;
            float r3 = fmaxf(v3, 0.f) + b0v.w;
            *(float4*)&out[(size_t)m * (2 * DOUT) + tx * 4] =
                make_float4(r0, r1, r2, r3);
            psum[0] += r0; psq[0] = fmaf(r0, r0, psq[0]);
            psum[1] += r1; psq[1] = fmaf(r1, r1, psq[1]);
            psum[2] += r2; psq[2] = fmaf(r2, r2, psq[2]);
            psum[3] += r3; psq[3] = fmaf(r3, r3, psq[3]);
            float y0 = half ? f2hi(acc2[p][4]) : f2lo(acc2[p][4]);
            float y1 = half ? f2hi(acc2[p][5]) : f2lo(acc2[p][5]);
            float y2 = half ? f2hi(acc2[p][6]) : f2lo(acc2[p][6]);
            float y3 = half ? f2hi(acc2[p][7]) : f2lo(acc2[p][7]);
            *(float4*)&g_y1[(size_t)m * DIN + tx * 4] =
                make_float4(y0, y1, y2, y3);
        }
    }

    // Stats: conflict-free shared staging, then one atomic pass
    *(float4*)&sred_s[ty][tx * 4] = make_float4(psum[0], psum[1], psum[2], psum[3]);
    *(float4*)&sred_q[ty][tx * 4] = make_float4(psq[0], psq[1], psq[2], psq[3]);
    __syncthreads();
    if (tid < 128) {
        float s = 0.f, q = 0.f;
#pragma unroll
        for (int w = 0; w < 8; w++) { s += sred_s[w][tid]; q += sred_q[w][tid]; }
        atomicAdd(&g_stats[tid], s);
        atomicAdd(&g_stats[256 + tid], q);
    }
}

// ---------------------------------------------------------------------------
// Fused SpMM: p1[n] = relu(sum_e val*Y1[col]) + b1 -> out[:,128:256],
// with p1 BN column stats fused in (smem reduction + global atomics).
// One warp per node, lane owns a float4. 4-edge unroll.
__global__ __launch_bounds__(256)
void spmm_fused_kernel(const float* __restrict__ vals,
                       const int*   __restrict__ cols,
                       const float* __restrict__ b1,
                       float* __restrict__ out,
                       int N) {
    __shared__ float s_sum[128], s_sq[128];
    int tid  = threadIdx.x;
    int warp = (blockIdx.x * blockDim.x + tid) >> 5;
    int lane = tid & 31;
    if (tid < 128) { s_sum[tid] = 0.f; s_sq[tid] = 0.f; }
    __syncthreads();

    if (warp < N) {
        int s = g_rowptr[warp];
        int e = g_rowptr[warp + 1];
        float4 acc0 = make_float4(0.f, 0.f, 0.f, 0.f);
        float4 acc1 = make_float4(0.f, 0.f, 0.f, 0.f);
        int t = s;
        for (; t + 3 < e; t += 4) {
            float v0 = __ldg(&vals[t]),     v1 = __ldg(&vals[t + 1]);
            float v2 = __ldg(&vals[t + 2]), v3 = __ldg(&vals[t + 3]);
            int c0 = __ldg(&cols[t]),     c1 = __ldg(&cols[t + 1]);
            int c2 = __ldg(&cols[t + 2]), c3 = __ldg(&cols[t + 3]);
            float4 x0 = __ldg(&((const float4*)&g_y1[(size_t)c0 * DIN])[lane]);
            float4 x1 = __ldg(&((const float4*)&g_y1[(size_t)c1 * DIN])[lane]);
            float4 x2 = __ldg(&((const float4*)&g_y1[(size_t)c2 * DIN])[lane]);
            float4 x3 = __ldg(&((const float4*)&g_y1[(size_t)c3 * DIN])[lane]);
            acc0.x = fmaf(v0, x0.x, acc0.x); acc0.y = fmaf(v0, x0.y, acc0.y);
            acc0.z = fmaf(v0, x0.z, acc0.z); acc0.w = fmaf(v0, x0.w, acc0.w);
            acc1.x = fmaf(v1, x1.x, acc1.x); acc1.y = fmaf(v1, x1.y, acc1.y);
            acc1.z = fmaf(v1, x1.z, acc1.z); acc1.w = fmaf(v1, x1.w, acc1.w);
            acc0.x = fmaf(v2, x2.x, acc0.x); acc0.y = fmaf(v2, x2.y, acc0.y);
            acc0.z = fmaf(v2, x2.z, acc0.z); acc0.w = fmaf(v2, x2.w, acc0.w);
            acc1.x = fmaf(v3, x3.x, acc1.x); acc1.y = fmaf(v3, x3.y, acc1.y);
            acc1.z = fmaf(v3, x3.z, acc1.z); acc1.w = fmaf(v3, x3.w, acc1.w);
        }
        for (; t < e; t++) {
            float v0 = __ldg(&vals[t]);
            int   c0 = __ldg(&cols[t]);
            float4 x0 = __ldg(&((const float4*)&g_y1[(size_t)c0 * DIN])[lane]);
            acc0.x = fmaf(v0, x0.x, acc0.x); acc0.y = fmaf(v0, x0.y, acc0.y);
            acc0.z = fmaf(v0, x0.z, acc0.z); acc0.w = fmaf(v0, x0.w, acc0.w);
        }
        float4 bb = __ldg(&((const float4*)b1)[lane]);
        float4 r;
        r.x = fmaxf(acc0.x + acc1.x, 0.f) + bb.x;
        r.y = fmaxf(acc0.y + acc1.y, 0.f) + bb.y;
        r.z = fmaxf(acc0.z + acc1.z, 0.f) + bb.z;
        r.w = fmaxf(acc0.w + acc1.w, 0.f) + bb.w;
        *(float4*)&out[(size_t)warp * (2 * DOUT) + DOUT + lane * 4] = r;
        // stats into smem (spread addresses; ~2 cyc/lane)
        atomicAdd(&s_sum[lane * 4 + 0], r.x);
        atomicAdd(&s_sum[lane * 4 + 1], r.y);
        atomicAdd(&s_sum[lane * 4 + 2], r.z);
        atomicAdd(&s_sum[lane * 4 + 3], r.w);
        atomicAdd(&s_sq[lane * 4 + 0], r.x * r.x);
        atomicAdd(&s_sq[lane * 4 + 1], r.y * r.y);
        atomicAdd(&s_sq[lane * 4 + 2], r.z * r.z);
        atomicAdd(&s_sq[lane * 4 + 3], r.w * r.w);
    }
    __syncthreads();
    if (tid < 128) {
        atomicAdd(&g_stats[128 + tid], s_sum[tid]);
        atomicAdd(&g_stats[384 + tid], s_sq[tid]);
    }
}

// ---------------------------------------------------------------------------
// Normalize one 128-col half of out; BN finalize inlined in the prologue.
// half=0 -> cols 0..127, half=1 -> cols 128..255.
__global__ __launch_bounds__(256)
void bn_apply_half_kernel(float* __restrict__ out,
                          const float* __restrict__ gamma,
                          const float* __restrict__ beta,
                          int N, int half) {
    __shared__ float scale[128], shift[128];
    int tid = threadIdx.x;
    if (tid < 128) {
        int c = half * 128 + tid;
        float inv_n = 1.0f / (float)N;
        float mean = g_stats[c] * inv_n;
        float var  = g_stats[256 + c] * inv_n - mean * mean;
        float s = __ldg(&gamma[c]) * rsqrtf(var + BN_EPS);
        scale[tid] = s;
        shift[tid] = __ldg(&beta[c]) - mean * s;
    }
    __syncthreads();

    size_t total = (size_t)N * 32;          // float4s in this half
    size_t i = (size_t)blockIdx.x * blockDim.x + tid;
    size_t stride = (size_t)gridDim.x * blockDim.x;
    const float4* scale4 = (const float4*)scale;
    const float4* shift4 = (const float4*)shift;
    for (; i < total; i += stride) {
        size_t row = i >> 5;
        int    q   = (int)(i & 31);
        float4 s  = scale4[q];
        float4 sh = shift4[q];
        size_t idx = row * 64 + half * 32 + q;
        float4 v = ((float4*)out)[idx];
        v.x = fmaf(v.x, s.x, sh.x);
        v.y = fmaf(v.y, s.y, sh.y);
        v.z = fmaf(v.z, s.z, sh.z);
        v.w = fmaf(v.w, s.w, sh.w);
        ((float4*)out)[idx] = v;
    }
}

// ---------------------------------------------------------------------------
extern "C" void kernel_launch(void* const* d_in, const int* in_sizes, int n_in,
                              void* d_out, int out_size) {
    const float* feat     = (const float*)d_in[0];
    const float* adj_vals = (const float*)d_in[1];
    const float* W0       = (const float*)d_in[2];
    const float* W1       = (const float*)d_in[3];
    const float* b0       = (const float*)d_in[4];
    const float* b1       = (const float*)d_in[5];
    const float* gamma    = (const float*)d_in[6];
    const float* beta     = (const float*)d_in[7];
    const int*   adj_rows = (const int*)d_in[8];
    const int*   adj_cols = (const int*)d_in[9];
    float* out = (float*)d_out;

    int N = in_sizes[0] / DIN;
    int E = in_sizes[1];

    // Side stream + events, created once on the eager correctness call
    // (before graph capture), reused inside capture via event fork/join.
    static cudaStream_t s1 = nullptr;
    static cudaEvent_t  eZ = nullptr, eR = nullptr, eD = nullptr, eA0 = nullptr;
    if (s1 == nullptr) {
        cudaStreamCreateWithFlags(&s1, cudaStreamNonBlocking);
        cudaEventCreateWithFlags(&eZ,  cudaEventDisableTiming);
        cudaEventCreateWithFlags(&eR,  cudaEventDisableTiming);
        cudaEventCreateWithFlags(&eD,  cudaEventDisableTiming);
        cudaEventCreateWithFlags(&eA0, cudaEventDisableTiming);
    }

    int gblocks = (N + 63) / 64;
    int sblocks = (N * 32 + 255) / 256;
    int ablocks = (N * 32 + 255) / 256;
    if (ablocks > 8192) ablocks = 8192;

    // main: zero stats, then FORK
    zero_stats_kernel<<<1, 512>>>();
    cudaEventRecord(eZ, 0);

    // side (forked): rowptr overlaps dgemm
    cudaStreamWaitEvent(s1, eZ, 0);
    build_rowptr_kernel<<<(E + 255) / 256, 256, 0, s1>>>(adj_rows, E, N);
    cudaEventRecord(eR, s1);

    // main: dgemm
    dgemm_kernel<<<gblocks, 256>>>(feat, W0, W1, b0, out, N);
    cudaEventRecord(eD, 0);

    // side: p0's BN half (finalize inlined) runs during spmm
    cudaStreamWaitEvent(s1, eD, 0);
    bn_apply_half_kernel<<<ablocks, 256, 0, s1>>>(out, gamma, beta, N, 0);
    cudaEventRecord(eA0, s1);

    // main: spmm (needs rowptr + Y1; stats fused) -> p1 BN half
    cudaStreamWaitEvent(0, eR, 0);
    spmm_fused_kernel<<<sblocks, 256>>>(adj_vals, adj_cols, b1, out, N);
    bn_apply_half_kernel<<<ablocks, 256>>>(out, gamma, beta, N, 1);

    // join side branch before capture ends
    cudaStreamWaitEvent(0, eA0, 0);
}